// round 15
// baseline (speedup 1.0000x reference)
#include <cuda_runtime.h>
#include <cstdint>
#include <math.h>

#define N     2048
#define NNZ   32768
#define KL    56
#define GRID  128
#define TPB   256
#define BKS   16
#define SYRK_TILES 136
#define SYRK_T 512
#define A_STRIDE 266          // dup-pair row (128 pairs + pad, conflict-free staging)
#define B_STRIDE 132
#define SYRK_SMEM ((2*BKS*A_STRIDE + 2*BKS*B_STRIDE) * 4)

// ---------------- scratch (device globals; no allocation) ------------------
__device__ float g_A[N*N];
__device__ float g_C[N*N];
__device__ float g_CT[N*N];
__device__ float g_M[N*N];

__device__ float g_vals[NNZ];
__device__ int   g_rowptr[N+1];
__device__ int   g_cnt[N];
__device__ int   g_colidx[NNZ];
__device__ float g_csrval[NNZ];

__device__ float g_u[2][N];
__device__ float g_part[2][GRID];
__device__ float g_alpha[KL];
__device__ float g_betav[KL];
__device__ unsigned int g_grp[8*32];      // group counters, 128B apart
__device__ unsigned int g_root;
__device__ volatile unsigned int g_release;

// ---------------- CSR build ------------------------------------------------
__global__ void k_prep(const float* __restrict__ pred, const float* __restrict__ scl) {
    int i = blockIdx.x * blockDim.x + threadIdx.x;
    if (i < NNZ) g_vals[i] = pred[i] * scl[i];
    if (i < N)   g_cnt[i] = 0;
    if (blockIdx.x == 0) {
        if (threadIdx.x < 8*32) g_grp[threadIdx.x] = 0;
        if (threadIdx.x == 0) { g_root = 0; g_release = 0; }
    }
}
__global__ void k_count(const int* __restrict__ rows) {
    int i = blockIdx.x * blockDim.x + threadIdx.x;
    if (i < NNZ) atomicAdd(&g_cnt[rows[i]], 1);
}
__global__ void k_scan() {
    int tid = threadIdx.x;
    int lane = tid & 31, warp = tid >> 5;
    int v[8]; int loc = 0;
#pragma unroll
    for (int u = 0; u < 8; u++) { v[u] = g_cnt[tid*8 + u]; loc += v[u]; }
    int sc = loc;
#pragma unroll
    for (int off = 1; off < 32; off <<= 1) {
        int nb = __shfl_up_sync(0xffffffffu, sc, off);
        if (lane >= off) sc += nb;
    }
    __shared__ int wsum[8];
    if (lane == 31) wsum[warp] = sc;
    __syncthreads();
    if (tid == 0) {
        int a = 0;
#pragma unroll
        for (int w = 0; w < 8; w++) { int t = wsum[w]; wsum[w] = a; a += t; }
    }
    __syncthreads();
    int run = sc - loc + wsum[warp];
#pragma unroll
    for (int u = 0; u < 8; u++) {
        g_rowptr[tid*8 + u] = run;
        g_cnt[tid*8 + u]    = run;
        run += v[u];
    }
    if (tid == 255) g_rowptr[N] = run;
}
__global__ void k_fill(const int* __restrict__ rows, const int* __restrict__ cols) {
    int i = blockIdx.x * blockDim.x + threadIdx.x;
    if (i < NNZ) {
        int p = atomicAdd(&g_cnt[rows[i]], 1);
        g_colidx[p] = cols[i];
        g_csrval[p] = g_vals[i];
    }
}

// ------ SYRK: A = Af*Af^T / N + I ------------------------------------------
// 136 CTAs, 512 threads. A duplicated as pairs in smem -> FFMA2 with direct
// LDS.64 broadcast operands (no MOV.b64 duplication). Bit-identical FMA order.
__global__ void __launch_bounds__(SYRK_T) k_syrk(const float* __restrict__ Af) {
    extern __shared__ float sm[];
#define AS(b,k,c) sm[((b)*BKS + (k))*A_STRIDE + (c)]
#define BS(b,k,c) sm[2*BKS*A_STRIDE + ((b)*BKS + (k))*B_STRIDE + (c)]

    int rem = blockIdx.x, by = 0;
    while (rem >= 16 - by) { rem -= 16 - by; by++; }
    const int bx = by + rem;

    const int tid = threadIdx.x;
    const int tx = tid & 31, ty = tid >> 5;
    const int row0 = by * 128, col0 = bx * 128;

    uint64_t acc2[8][2];
#pragma unroll
    for (int i = 0; i < 8; i++) { acc2[i][0] = 0ull; acc2[i][1] = 0ull; }

    const int lr = tid >> 2;            // 0..127
    const int lk = (tid & 3) * 4;       // 0,4,8,12
    const float* abase = Af + (size_t)(row0 + lr) * N + lk;
    const float* bbase = Af + (size_t)(col0 + lr) * N + lk;

    float4 pa = *(const float4*)(abase);
    float4 pb = *(const float4*)(bbase);
    {   // stage tile 0 into buffer 0 (A duplicated as pairs)
        *(float2*)&AS(0, lk+0, 2*lr) = make_float2(pa.x, pa.x);
        *(float2*)&AS(0, lk+1, 2*lr) = make_float2(pa.y, pa.y);
        *(float2*)&AS(0, lk+2, 2*lr) = make_float2(pa.z, pa.z);
        *(float2*)&AS(0, lk+3, 2*lr) = make_float2(pa.w, pa.w);
        BS(0, lk+0, lr) = pb.x; BS(0, lk+1, lr) = pb.y;
        BS(0, lk+2, lr) = pb.z; BS(0, lk+3, lr) = pb.w;
    }
    __syncthreads();

    const int NIT = N / BKS;       // 128
    for (int it = 0; it < NIT; it++) {
        const int buf = it & 1;
        if (it + 1 < NIT) {
            int off = (it + 1) * BKS;
            pa = *(const float4*)(abase + off);
            pb = *(const float4*)(bbase + off);
        }
#pragma unroll
        for (int k = 0; k < BKS; k++) {
            const uint64_t* arow = (const uint64_t*)&AS(buf, k, 0);
            const uint64_t* bq   = (const uint64_t*)&BS(buf, k, 4*tx);
            uint64_t bp0 = bq[0], bp1 = bq[1];
            uint64_t ap[8];
#pragma unroll
            for (int j = 0; j < 4; j++) {
                ap[j]   = arow[4*ty + j];
                ap[4+j] = arow[64 + 4*ty + j];
            }
#pragma unroll
            for (int i = 0; i < 8; i++) {
                asm("fma.rn.f32x2 %0, %1, %2, %0;" : "+l"(acc2[i][0]) : "l"(ap[i]), "l"(bp0));
                asm("fma.rn.f32x2 %0, %1, %2, %0;" : "+l"(acc2[i][1]) : "l"(ap[i]), "l"(bp1));
            }
        }
        if (it + 1 < NIT) {
            const int nb = buf ^ 1;
            *(float2*)&AS(nb, lk+0, 2*lr) = make_float2(pa.x, pa.x);
            *(float2*)&AS(nb, lk+1, 2*lr) = make_float2(pa.y, pa.y);
            *(float2*)&AS(nb, lk+2, 2*lr) = make_float2(pa.z, pa.z);
            *(float2*)&AS(nb, lk+3, 2*lr) = make_float2(pa.w, pa.w);
            BS(nb, lk+0, lr) = pb.x; BS(nb, lk+1, lr) = pb.y;
            BS(nb, lk+2, lr) = pb.z; BS(nb, lk+3, lr) = pb.w;
        }
        __syncthreads();
    }

    float acc[8][4];
#pragma unroll
    for (int i = 0; i < 8; i++)
#pragma unroll
        for (int j = 0; j < 2; j++) {
            float lo, hi;
            asm("mov.b64 {%0, %1}, %2;" : "=f"(lo), "=f"(hi) : "l"(acc2[i][j]));
            acc[i][2*j]   = lo;
            acc[i][2*j+1] = hi;
        }

    float invn = 1.0f / (float)N;
#pragma unroll
    for (int i = 0; i < 8; i++) {
        int gi = row0 + ((i<4) ? (4*ty+i) : (64+4*ty+i-4));
#pragma unroll
        for (int j = 0; j < 4; j++) {
            int gj = col0 + 4*tx + j;
            float val = acc[i][j]*invn + ((gi==gj)?1.0f:0.0f);
            g_A[(size_t)gi*N+gj] = val;
            if (bx > by) g_A[(size_t)gj*N+gi] = val;
        }
    }
#undef AS
#undef BS
}

// ---------------- SpMM 1: C = S * A ------------------------------------------
__global__ void k_spmm_AC() {
    int r = blockIdx.x, t = threadIdx.x;
    int s = g_rowptr[r], e = g_rowptr[r+1];
    float acc[8] = {0,0,0,0,0,0,0,0};
    for (int k = s; k < e; k++) {
        int c = g_colidx[k];
        float v = g_csrval[k];
        const float* xr = g_A + (size_t)c * N;
#pragma unroll
        for (int u = 0; u < 8; u++) acc[u] += v * xr[t + u*TPB];
    }
    float* yr = g_C + (size_t)r * N;
#pragma unroll
    for (int u = 0; u < 8; u++) yr[t + u*TPB] = acc[u];
}

// ---------------- transpose: CT = C^T ----------------------------------------
__global__ void k_tr_C_CT() {
    __shared__ float t[32][33];
    int bx = blockIdx.x*32, by = blockIdx.y*32;
    int x = bx + threadIdx.x;
#pragma unroll
    for (int j = 0; j < 32; j += 8)
        t[threadIdx.y+j][threadIdx.x] = g_C[(size_t)(by+threadIdx.y+j)*N + x];
    __syncthreads();
    int x2 = by + threadIdx.x;
#pragma unroll
    for (int j = 0; j < 32; j += 8)
        g_CT[(size_t)(bx+threadIdx.y+j)*N + x2] = t[threadIdx.x][threadIdx.y+j];
}

// ------- SpMM 2 fused: M = A + C + C^T + S*C^T ------------------------------
__global__ void k_spmm_M() {
    int r = blockIdx.x, t = threadIdx.x;
    int s = g_rowptr[r], e = g_rowptr[r+1];
    float acc[8] = {0,0,0,0,0,0,0,0};
    for (int k = s; k < e; k++) {
        int c = g_colidx[k];
        float v = g_csrval[k];
        const float* xr = g_CT + (size_t)c * N;
#pragma unroll
        for (int u = 0; u < 8; u++) acc[u] += v * xr[t + u*TPB];
    }
    const float* ar = g_A  + (size_t)r * N;
    const float* cr = g_C  + (size_t)r * N;
    const float* tr = g_CT + (size_t)r * N;
    float* mr = g_M + (size_t)r * N;
#pragma unroll
    for (int u = 0; u < 8; u++) {
        int i = t + u*TPB;
        mr[i] = ar[i] + cr[i] + tr[i] + acc[u];
    }
}

// ------ Lanczos: persistent, tree grid barrier (8 groups x 16 blocks) ------
__device__ __forceinline__ void gbar(unsigned int& ep) {
    ep++;
    __threadfence();
    __syncthreads();
    if (threadIdx.x == 0) {
        int g = blockIdx.x >> 4;
        unsigned int old = atomicAdd(&g_grp[g*32], 1u);
        if (old == ep*16u - 1u) {
            unsigned int old2 = atomicAdd(&g_root, 1u);
            if (old2 == ep*8u - 1u) {
                __threadfence();
                g_release = ep;
            }
        }
        while (g_release < ep) { }
    }
    __syncthreads();
    __threadfence();
}

__device__ __forceinline__ float sum_parts(const float* part, float* sred, float* sbc) {
    int tid = threadIdx.x, warp = tid >> 5, wl = tid & 31;
    float a = (tid < GRID) ? __ldcg(&part[tid]) : 0.f;
#pragma unroll
    for (int off = 16; off; off >>= 1) a += __shfl_down_sync(0xffffffffu, a, off);
    if (wl == 0) sred[warp] = a;
    __syncthreads();
    if (tid == 0) {
        float s = 0.f;
#pragma unroll
        for (int w = 0; w < 4; w++) s += sred[w];
        sbc[0] = s;
    }
    __syncthreads();
    return sbc[0];
}

__device__ __forceinline__ float block_sum(float p, float* sred, float* sbc) {
    int tid = threadIdx.x, warp = tid >> 5, wl = tid & 31;
#pragma unroll
    for (int off = 16; off; off >>= 1) p += __shfl_down_sync(0xffffffffu, p, off);
    if (wl == 0) sred[warp] = p;
    __syncthreads();
    if (tid == 0) {
        float s = 0.f;
#pragma unroll
        for (int w = 0; w < 8; w++) s += sred[w];
        sbc[0] = s;
    }
    __syncthreads();
    return sbc[0];
}

__global__ void __launch_bounds__(TPB) k_lanczos() {
    __shared__ __align__(16) float svbuf[2][N];
    __shared__ float shw[16];
    __shared__ float sred[8];
    __shared__ float sbc[1];

    const int tid = threadIdx.x, bid = blockIdx.x;
    const int q = tid >> 4, lane = tid & 15;
    const int row = bid*16 + q;
    const int myrow = bid*16 + tid;
    unsigned int ep = 0;

    if (tid < 16) {
        unsigned int h = (unsigned int)myrow * 2654435761u + 0x9E3779B9u;
        h ^= h>>16; h *= 0x85ebca6bu; h ^= h>>13; h *= 0xc2b2ae35u; h ^= h>>16;
        g_u[1][myrow] = (float)(h & 0xffffu) * (1.0f/65536.0f) + 0.0625f;
    }
    gbar(ep);

    float* svc = svbuf[0];
    float* svp = svbuf[1];
    {
        float p = 0.f;
        for (int i = tid; i < N; i += TPB) {
            float x = __ldcg(&g_u[1][i]);
            svc[i] = x;
            svp[i] = 0.f;
            p += x * x;
        }
        float n0 = block_sum(p, sred, sbc);
        float inv0 = rsqrtf(n0);
        for (int i = tid; i < N; i += TPB) svc[i] *= inv0;
        __syncthreads();
    }
    float beta_p = 0.f;

    for (int j = 0; j < KL; j++) {
        const int b = j & 1;
        const float4* M4  = ((const float4*)g_M) + (size_t)row * (N/4);
        const float4* sv4 = (const float4*)svc;
        float s = 0.f;
#pragma unroll
        for (int t = 0; t < 16; t++) {
            int qi = lane*2 + t*32;
            float4 m0 = M4[qi], m1 = M4[qi+1];
            float4 x0 = sv4[qi], x1 = sv4[qi+1];
            s += m0.x*x0.x + m0.y*x0.y + m0.z*x0.z + m0.w*x0.w
               + m1.x*x1.x + m1.y*x1.y + m1.z*x1.z + m1.w*x1.w;
        }
#pragma unroll
        for (int off = 8; off; off >>= 1) s += __shfl_down_sync(0xffffffffu, s, off, 16);
        if (lane == 0) shw[q] = s;
        __syncthreads();

        float pa = 0.f;
        if (tid < 16) {
            float uval = shw[tid];
            g_u[b][myrow] = uval;
            pa = uval * svc[myrow];
        }
#pragma unroll
        for (int off = 8; off; off >>= 1) pa += __shfl_down_sync(0xffffffffu, pa, off, 16);
        if (tid == 0) g_part[b][bid] = pa;
        gbar(ep);

        float alpha = sum_parts(g_part[b], sred, sbc);
        float pw = 0.f;
        for (int i = tid; i < N; i += TPB) {
            float w = __ldcg(&g_u[b][i]) - alpha*svc[i] - beta_p*svp[i];
            svp[i] = w;
            pw += w * w;
        }
        float nw = block_sum(pw, sred, sbc);
        float beta = sqrtf(fmaxf(nw, 1e-30f));
        if (bid == 0 && tid == 0) { g_alpha[j] = alpha; g_betav[j] = beta; }
        float invb = 1.0f / beta;
        for (int i = tid; i < N; i += TPB) svp[i] *= invb;
        __syncthreads();
        float* t = svc; svc = svp; svp = t;
        beta_p = beta;
    }
}

// ------- extremes: DIVISION-FREE Sturm (sign-change count), 4 steps --------
__global__ void k_extremes(float* out) {
    __shared__ double sa[KL], sbb[KL];
    __shared__ double sbounds[2];
    __shared__ double res[2];
    int tid = threadIdx.x;
    int warp = tid >> 5, lane = tid & 31;

    for (int i = tid; i < KL; i += 64) {
        sa[i] = (double)g_alpha[i];
        double b = (double)g_betav[i];
        sbb[i] = b * b;
    }
    __syncthreads();
    if (tid == 0) {
        double lo = 1e300, hi = -1e300;
        for (int i = 0; i < KL; i++) {
            double bl = (i > 0)    ? sqrt(sbb[i-1]) : 0.0;
            double br = (i < KL-1) ? sqrt(sbb[i])   : 0.0;
            double a = sa[i];
            if (a - bl - br < lo) lo = a - bl - br;
            if (a + bl + br > hi) hi = a + bl + br;
        }
        sbounds[0] = lo; sbounds[1] = hi;
    }
    __syncthreads();

    int target = (warp == 0) ? KL : 1;
    double lo = sbounds[0], hi = sbounds[1];

    for (int step = 0; step < 4; step++) {
        double w = (hi - lo) * (1.0 / 33.0);
        double x = lo + w * (double)(lane + 1);
        // count eigenvalues < x = sign changes in {p_0=1, p_1, ..., p_KL}
        double p2 = 1.0;
        double p1 = sa[0] - x;
        int cnt = (p1 < 0.0);
        for (int i = 1; i < KL; i++) {
            double pi = (sa[i] - x) * p1 - sbb[i-1] * p2;
            cnt += ((pi < 0.0) != (p1 < 0.0));
            double apv = fabs(pi);
            double sc = 1.0;
            if (apv > 1e120) sc = 1e-120;
            else if (apv < 1e-120 && apv > 0.0) sc = 1e120;
            p2 = p1 * sc;
            p1 = pi * sc;
        }
        unsigned mask = __ballot_sync(0xffffffffu, cnt >= target);
        int first = (mask == 0u) ? 32 : (__ffs(mask) - 1);
        if (first < 32) hi = lo + w * (double)(first + 1);
        lo = lo + w * (double)first;
    }
    if (lane == 0) res[warp] = 0.5 * (lo + hi);
    __syncthreads();
    if (tid == 0) {
        double lmax = fmax(res[0], 1e-12);
        double lmin = fmax(res[1], 1e-12);
        out[0] = (float)(log(lmax) - log(lmin));
    }
}

// ---------------- launch ------------------------------------------------------
extern "C" void kernel_launch(void* const* d_in, const int* in_sizes, int n_in,
                              void* d_out, int out_size) {
    const float* pred = (const float*)d_in[0];
    const float* scl  = (const float*)d_in[1];
    const float* Af   = (const float*)d_in[2];
    const int* frows  = (const int*)d_in[3];
    const int* fcols  = (const int*)d_in[4];
    float* out = (float*)d_out;

    cudaFuncSetAttribute(k_syrk, cudaFuncAttributeMaxDynamicSharedMemorySize, SYRK_SMEM);

    k_prep <<<NNZ/TPB, TPB>>>(pred, scl);
    k_count<<<NNZ/TPB, TPB>>>(frows);
    k_scan <<<1, 256>>>();
    k_syrk <<<SYRK_TILES, SYRK_T, SYRK_SMEM>>>(Af);   // 4th launch -> ncu
    k_fill <<<NNZ/TPB, TPB>>>(frows, fcols);

    k_spmm_AC <<<N, TPB>>>();
    k_tr_C_CT <<<dim3(64,64), dim3(32,8)>>>();
    k_spmm_M  <<<N, TPB>>>();

    k_lanczos <<<GRID, TPB>>>();
    k_extremes<<<1, 64>>>(out);
}

// round 16
// speedup vs baseline: 1.2356x; 1.2356x over previous
#include <cuda_runtime.h>
#include <cstdint>
#include <math.h>

#define N     2048
#define NNZ   32768
#define KL    52
#define GRID  128
#define TPB   256
#define BKS   16
#define SYRK_TILES 136

// ---------------- scratch (device globals; no allocation) ------------------
__device__ float g_A[N*N];
__device__ float g_C[N*N];
__device__ float g_CT[N*N];
__device__ float g_M[N*N];

__device__ float g_vals[NNZ];
__device__ int   g_rowptr[N+1];
__device__ int   g_cnt[N];
__device__ int   g_colidx[NNZ];
__device__ float g_csrval[NNZ];

__device__ float g_u[2][N];
__device__ float g_part[2][GRID];
__device__ float g_alpha[KL];
__device__ float g_betav[KL];
__device__ unsigned int g_barcnt;
__device__ volatile unsigned int g_release;

// ---------------- CSR build ------------------------------------------------
__global__ void k_prep(const float* __restrict__ pred, const float* __restrict__ scl) {
    int i = blockIdx.x * blockDim.x + threadIdx.x;
    if (i < NNZ) g_vals[i] = pred[i] * scl[i];
    if (i < N)   g_cnt[i] = 0;
    if (blockIdx.x == 0 && threadIdx.x == 0) { g_barcnt = 0; g_release = 0; }
}
__global__ void k_count(const int* __restrict__ rows) {
    int i = blockIdx.x * blockDim.x + threadIdx.x;
    if (i < NNZ) atomicAdd(&g_cnt[rows[i]], 1);
}
__global__ void k_scan() {
    int tid = threadIdx.x;
    int lane = tid & 31, warp = tid >> 5;
    int v[8]; int loc = 0;
#pragma unroll
    for (int u = 0; u < 8; u++) { v[u] = g_cnt[tid*8 + u]; loc += v[u]; }
    int sc = loc;
#pragma unroll
    for (int off = 1; off < 32; off <<= 1) {
        int nb = __shfl_up_sync(0xffffffffu, sc, off);
        if (lane >= off) sc += nb;
    }
    __shared__ int wsum[8];
    if (lane == 31) wsum[warp] = sc;
    __syncthreads();
    if (tid == 0) {
        int a = 0;
#pragma unroll
        for (int w = 0; w < 8; w++) { int t = wsum[w]; wsum[w] = a; a += t; }
    }
    __syncthreads();
    int run = sc - loc + wsum[warp];
#pragma unroll
    for (int u = 0; u < 8; u++) {
        g_rowptr[tid*8 + u] = run;
        g_cnt[tid*8 + u]    = run;
        run += v[u];
    }
    if (tid == 255) g_rowptr[N] = run;
}
__global__ void k_fill(const int* __restrict__ rows, const int* __restrict__ cols) {
    int i = blockIdx.x * blockDim.x + threadIdx.x;
    if (i < NNZ) {
        int p = atomicAdd(&g_cnt[rows[i]], 1);
        g_colidx[p] = cols[i];
        g_csrval[p] = g_vals[i];
    }
}

// ------ SYRK: A = Af*Af^T / N + I (R13 best config: 256 thr, BK=16, dbuf) --
__global__ void __launch_bounds__(256) k_syrk(const float* __restrict__ Af) {
    int rem = blockIdx.x, by = 0;
    while (rem >= 16 - by) { rem -= 16 - by; by++; }
    const int bx = by + rem;

    __shared__ __align__(16) float As[2][BKS][132];
    __shared__ __align__(16) float Bs[2][BKS][132];
    const int tid = threadIdx.x;
    const int tx = tid & 15, ty = tid >> 4;
    const int row0 = by * 128, col0 = bx * 128;

    uint64_t acc2[8][4];
#pragma unroll
    for (int i = 0; i < 8; i++)
#pragma unroll
        for (int j = 0; j < 4; j++) acc2[i][j] = 0ull;

    const int lr = tid >> 1;
    const int lk = (tid & 1) * 8;
    const float* abase = Af + (size_t)(row0 + lr) * N + lk;
    const float* bbase = Af + (size_t)(col0 + lr) * N + lk;

    float4 pa0 = *(const float4*)(abase);
    float4 pa1 = *(const float4*)(abase + 4);
    float4 pb0 = *(const float4*)(bbase);
    float4 pb1 = *(const float4*)(bbase + 4);
    {
        As[0][lk+0][lr]=pa0.x; As[0][lk+1][lr]=pa0.y; As[0][lk+2][lr]=pa0.z; As[0][lk+3][lr]=pa0.w;
        As[0][lk+4][lr]=pa1.x; As[0][lk+5][lr]=pa1.y; As[0][lk+6][lr]=pa1.z; As[0][lk+7][lr]=pa1.w;
        Bs[0][lk+0][lr]=pb0.x; Bs[0][lk+1][lr]=pb0.y; Bs[0][lk+2][lr]=pb0.z; Bs[0][lk+3][lr]=pb0.w;
        Bs[0][lk+4][lr]=pb1.x; Bs[0][lk+5][lr]=pb1.y; Bs[0][lk+6][lr]=pb1.z; Bs[0][lk+7][lr]=pb1.w;
    }
    __syncthreads();

    const int NIT = N / BKS;
    for (int it = 0; it < NIT; it++) {
        const int buf = it & 1;
        if (it + 1 < NIT) {
            int off = (it + 1) * BKS;
            pa0 = *(const float4*)(abase + off);
            pa1 = *(const float4*)(abase + off + 4);
            pb0 = *(const float4*)(bbase + off);
            pb1 = *(const float4*)(bbase + off + 4);
        }
#pragma unroll
        for (int k = 0; k < BKS; k++) {
            float4 a0 = *(const float4*)&As[buf][k][4*ty];
            float4 a1 = *(const float4*)&As[buf][k][64+4*ty];
            const uint64_t* bq0 = (const uint64_t*)&Bs[buf][k][4*tx];
            const uint64_t* bq1 = (const uint64_t*)&Bs[buf][k][64+4*tx];
            uint64_t bp0 = bq0[0], bp1 = bq0[1], bp2 = bq1[0], bp3 = bq1[1];
            float av[8] = {a0.x,a0.y,a0.z,a0.w,a1.x,a1.y,a1.z,a1.w};
#pragma unroll
            for (int i = 0; i < 8; i++) {
                uint64_t ap;
                asm("mov.b64 %0, {%1, %1};" : "=l"(ap) : "f"(av[i]));
                asm("fma.rn.f32x2 %0, %1, %2, %0;" : "+l"(acc2[i][0]) : "l"(ap), "l"(bp0));
                asm("fma.rn.f32x2 %0, %1, %2, %0;" : "+l"(acc2[i][1]) : "l"(ap), "l"(bp1));
                asm("fma.rn.f32x2 %0, %1, %2, %0;" : "+l"(acc2[i][2]) : "l"(ap), "l"(bp2));
                asm("fma.rn.f32x2 %0, %1, %2, %0;" : "+l"(acc2[i][3]) : "l"(ap), "l"(bp3));
            }
        }
        if (it + 1 < NIT) {
            const int nb = buf ^ 1;
            As[nb][lk+0][lr]=pa0.x; As[nb][lk+1][lr]=pa0.y; As[nb][lk+2][lr]=pa0.z; As[nb][lk+3][lr]=pa0.w;
            As[nb][lk+4][lr]=pa1.x; As[nb][lk+5][lr]=pa1.y; As[nb][lk+6][lr]=pa1.z; As[nb][lk+7][lr]=pa1.w;
            Bs[nb][lk+0][lr]=pb0.x; Bs[nb][lk+1][lr]=pb0.y; Bs[nb][lk+2][lr]=pb0.z; Bs[nb][lk+3][lr]=pb0.w;
            Bs[nb][lk+4][lr]=pb1.x; Bs[nb][lk+5][lr]=pb1.y; Bs[nb][lk+6][lr]=pb1.z; Bs[nb][lk+7][lr]=pb1.w;
        }
        __syncthreads();
    }

    float acc[8][8];
#pragma unroll
    for (int i = 0; i < 8; i++)
#pragma unroll
        for (int j = 0; j < 4; j++) {
            float lo, hi;
            asm("mov.b64 {%0, %1}, %2;" : "=f"(lo), "=f"(hi) : "l"(acc2[i][j]));
            acc[i][2*j]   = lo;
            acc[i][2*j+1] = hi;
        }

    float invn = 1.0f / (float)N;
#pragma unroll
    for (int i = 0; i < 8; i++) {
        int gi = row0 + ((i<4) ? (4*ty+i) : (64+4*ty+i-4));
#pragma unroll
        for (int j = 0; j < 8; j++) {
            int gj = col0 + ((j<4) ? (4*tx+j) : (64+4*tx+j-4));
            float val = acc[i][j]*invn + ((gi==gj)?1.0f:0.0f);
            g_A[(size_t)gi*N+gj] = val;
            if (bx > by) g_A[(size_t)gj*N+gi] = val;
        }
    }
}

// ---------------- SpMM 1: C = S * A ------------------------------------------
__global__ void k_spmm_AC() {
    int r = blockIdx.x, t = threadIdx.x;
    int s = g_rowptr[r], e = g_rowptr[r+1];
    float acc[8] = {0,0,0,0,0,0,0,0};
    for (int k = s; k < e; k++) {
        int c = g_colidx[k];
        float v = g_csrval[k];
        const float* xr = g_A + (size_t)c * N;
#pragma unroll
        for (int u = 0; u < 8; u++) acc[u] += v * xr[t + u*TPB];
    }
    float* yr = g_C + (size_t)r * N;
#pragma unroll
    for (int u = 0; u < 8; u++) yr[t + u*TPB] = acc[u];
}

// ---------------- transpose: CT = C^T ----------------------------------------
__global__ void k_tr_C_CT() {
    __shared__ float t[32][33];
    int bx = blockIdx.x*32, by = blockIdx.y*32;
    int x = bx + threadIdx.x;
#pragma unroll
    for (int j = 0; j < 32; j += 8)
        t[threadIdx.y+j][threadIdx.x] = g_C[(size_t)(by+threadIdx.y+j)*N + x];
    __syncthreads();
    int x2 = by + threadIdx.x;
#pragma unroll
    for (int j = 0; j < 32; j += 8)
        g_CT[(size_t)(bx+threadIdx.y+j)*N + x2] = t[threadIdx.x][threadIdx.y+j];
}

// ------- SpMM 2 fused: M = A + C + C^T + S*C^T ------------------------------
__global__ void k_spmm_M() {
    int r = blockIdx.x, t = threadIdx.x;
    int s = g_rowptr[r], e = g_rowptr[r+1];
    float acc[8] = {0,0,0,0,0,0,0,0};
    for (int k = s; k < e; k++) {
        int c = g_colidx[k];
        float v = g_csrval[k];
        const float* xr = g_CT + (size_t)c * N;
#pragma unroll
        for (int u = 0; u < 8; u++) acc[u] += v * xr[t + u*TPB];
    }
    const float* ar = g_A  + (size_t)r * N;
    const float* cr = g_C  + (size_t)r * N;
    const float* tr = g_CT + (size_t)r * N;
    float* mr = g_M + (size_t)r * N;
#pragma unroll
    for (int u = 0; u < 8; u++) {
        int i = t + u*TPB;
        mr[i] = ar[i] + cr[i] + tr[i] + acc[u];
    }
}

// ---------------- Lanczos + fused extremes ----------------------------------
__device__ __forceinline__ void gbar(unsigned int& ep) {
    ep++;
    __threadfence();
    __syncthreads();
    if (threadIdx.x == 0) {
        unsigned int old = atomicAdd(&g_barcnt, 1u);
        if (old == GRID - 1u) {
            g_barcnt = 0;
            __threadfence();
            g_release = ep;
        } else {
            while (g_release < ep) { }
        }
    }
    __syncthreads();
    __threadfence();
}

__device__ __forceinline__ float sum_parts(const float* part, float* sred, float* sbc) {
    int tid = threadIdx.x, warp = tid >> 5, wl = tid & 31;
    float a = (tid < GRID) ? __ldcg(&part[tid]) : 0.f;
#pragma unroll
    for (int off = 16; off; off >>= 1) a += __shfl_down_sync(0xffffffffu, a, off);
    if (wl == 0) sred[warp] = a;
    __syncthreads();
    if (tid == 0) {
        float s = 0.f;
#pragma unroll
        for (int w = 0; w < 4; w++) s += sred[w];
        sbc[0] = s;
    }
    __syncthreads();
    return sbc[0];
}

__device__ __forceinline__ float block_sum(float p, float* sred, float* sbc) {
    int tid = threadIdx.x, warp = tid >> 5, wl = tid & 31;
#pragma unroll
    for (int off = 16; off; off >>= 1) p += __shfl_down_sync(0xffffffffu, p, off);
    if (wl == 0) sred[warp] = p;
    __syncthreads();
    if (tid == 0) {
        float s = 0.f;
#pragma unroll
        for (int w = 0; w < 8; w++) s += sred[w];
        sbc[0] = s;
    }
    __syncthreads();
    return sbc[0];
}

__global__ void __launch_bounds__(TPB) k_lanczos(float* out) {
    __shared__ __align__(16) float svbuf[2][N];
    __shared__ float shw[16];
    __shared__ float sred[8];
    __shared__ float sbc[1];

    const int tid = threadIdx.x, bid = blockIdx.x;
    const int q = tid >> 4, lane = tid & 15;
    const int row = bid*16 + q;
    const int myrow = bid*16 + tid;
    unsigned int ep = 0;

    if (tid < 16) {
        unsigned int h = (unsigned int)myrow * 2654435761u + 0x9E3779B9u;
        h ^= h>>16; h *= 0x85ebca6bu; h ^= h>>13; h *= 0xc2b2ae35u; h ^= h>>16;
        g_u[1][myrow] = (float)(h & 0xffffu) * (1.0f/65536.0f) + 0.0625f;
    }
    gbar(ep);

    float* svc = svbuf[0];
    float* svp = svbuf[1];
    {
        float p = 0.f;
        for (int i = tid; i < N; i += TPB) {
            float x = __ldcg(&g_u[1][i]);
            svc[i] = x;
            svp[i] = 0.f;
            p += x * x;
        }
        float n0 = block_sum(p, sred, sbc);
        float inv0 = rsqrtf(n0);
        for (int i = tid; i < N; i += TPB) svc[i] *= inv0;
        __syncthreads();
    }
    float beta_p = 0.f;

    for (int j = 0; j < KL; j++) {
        const int b = j & 1;
        const float4* M4  = ((const float4*)g_M) + (size_t)row * (N/4);
        const float4* sv4 = (const float4*)svc;
        float s = 0.f;
#pragma unroll
        for (int t = 0; t < 16; t++) {
            int qi = lane*2 + t*32;
            float4 m0 = M4[qi], m1 = M4[qi+1];
            float4 x0 = sv4[qi], x1 = sv4[qi+1];
            s += m0.x*x0.x + m0.y*x0.y + m0.z*x0.z + m0.w*x0.w
               + m1.x*x1.x + m1.y*x1.y + m1.z*x1.z + m1.w*x1.w;
        }
#pragma unroll
        for (int off = 8; off; off >>= 1) s += __shfl_down_sync(0xffffffffu, s, off, 16);
        if (lane == 0) shw[q] = s;
        __syncthreads();

        float pa = 0.f;
        if (tid < 16) {
            float uval = shw[tid];
            g_u[b][myrow] = uval;
            pa = uval * svc[myrow];
        }
#pragma unroll
        for (int off = 8; off; off >>= 1) pa += __shfl_down_sync(0xffffffffu, pa, off, 16);
        if (tid == 0) g_part[b][bid] = pa;
        gbar(ep);

        float alpha = sum_parts(g_part[b], sred, sbc);
        float pw = 0.f;
        for (int i = tid; i < N; i += TPB) {
            float w = __ldcg(&g_u[b][i]) - alpha*svc[i] - beta_p*svp[i];
            svp[i] = w;
            pw += w * w;
        }
        float nw = block_sum(pw, sred, sbc);
        float beta = sqrtf(fmaxf(nw, 1e-30f));
        if (bid == 0 && tid == 0) { g_alpha[j] = alpha; g_betav[j] = beta; }
        float invb = 1.0f / beta;
        for (int i = tid; i < N; i += TPB) svp[i] *= invb;
        __syncthreads();
        float* t = svc; svc = svp; svp = t;
        beta_p = beta;
    }

    // ---- fused extremes: block 0 only, 2 warps, double Sturm multisection
    if (bid != 0) return;
    __shared__ double sa[KL], sb[KL];
    __shared__ double sbounds[2];
    __shared__ double res[2];
    // block-0's own writes to g_alpha/g_betav are visible after __syncthreads
    for (int i = tid; i < KL; i += TPB) {
        sa[i] = (double)g_alpha[i];
        sb[i] = (double)g_betav[i];
    }
    __syncthreads();
    if (tid == 0) {
        double lo = 1e300, hi = -1e300;
        for (int i = 0; i < KL; i++) {
            double bl = (i > 0)    ? fabs(sb[i-1]) : 0.0;
            double br = (i < KL-1) ? fabs(sb[i])   : 0.0;
            double a = sa[i];
            if (a - bl - br < lo) lo = a - bl - br;
            if (a + bl + br > hi) hi = a + bl + br;
        }
        sbounds[0] = lo; sbounds[1] = hi;
    }
    __syncthreads();
    if (tid < 64) {
        int warp = tid >> 5, wl = tid & 31;
        int target = (warp == 0) ? KL : 1;
        double lo = sbounds[0], hi = sbounds[1];
        for (int step = 0; step < 4; step++) {
            double w = (hi - lo) * (1.0 / 33.0);
            double x = lo + w * (double)(wl + 1);
            double d = sa[0] - x;
            int cnt = (d < 0.0);
            for (int i = 1; i < KL; i++) {
                double den = d;
                if (fabs(den) < 1e-280) den = (den < 0.0) ? -1e-280 : 1e-280;
                d = (sa[i] - x) - sb[i-1]*sb[i-1] / den;
                cnt += (d < 0.0);
            }
            unsigned mask = __ballot_sync(0xffffffffu, cnt >= target);
            int first = (mask == 0u) ? 32 : (__ffs(mask) - 1);
            if (first < 32) hi = lo + w * (double)(first + 1);
            lo = lo + w * (double)first;
        }
        if (wl == 0) res[warp] = 0.5 * (lo + hi);
    }
    __syncthreads();
    if (tid == 0) {
        double lmax = fmax(res[0], 1e-12);
        double lmin = fmax(res[1], 1e-12);
        out[0] = (float)(log(lmax) - log(lmin));
    }
}

// ---------------- launch ------------------------------------------------------
extern "C" void kernel_launch(void* const* d_in, const int* in_sizes, int n_in,
                              void* d_out, int out_size) {
    const float* pred = (const float*)d_in[0];
    const float* scl  = (const float*)d_in[1];
    const float* Af   = (const float*)d_in[2];
    const int* frows  = (const int*)d_in[3];
    const int* fcols  = (const int*)d_in[4];
    float* out = (float*)d_out;

    k_prep <<<NNZ/TPB, TPB>>>(pred, scl);
    k_count<<<NNZ/TPB, TPB>>>(frows);
    k_scan <<<1, 256>>>();
    k_syrk <<<SYRK_TILES, 256>>>(Af);   // 4th launch -> captured by ncu
    k_fill <<<NNZ/TPB, TPB>>>(frows, fcols);

    k_spmm_AC <<<N, TPB>>>();
    k_tr_C_CT <<<dim3(64,64), dim3(32,8)>>>();
    k_spmm_M  <<<N, TPB>>>();

    k_lanczos <<<GRID, TPB>>>(out);
}

// round 17
// speedup vs baseline: 1.2399x; 1.0035x over previous
#include <cuda_runtime.h>
#include <cstdint>
#include <math.h>

#define N     2048
#define NNZ   32768
#define KL    52
#define GRID  128
#define TPB   256
#define BKS   16
#define SYRK_TILES 136

// ---------------- scratch (device globals; no allocation) ------------------
__device__ float g_A[N*N];
__device__ float g_C[N*N];
__device__ float g_CT[N*N];
__device__ float g_M[N*N];

__device__ float g_vals[NNZ];
__device__ int   g_rowptr[N+1];
__device__ int   g_cnt[N];
__device__ int   g_colidx[NNZ];
__device__ float g_csrval[NNZ];

__device__ float g_u[2][N];
__device__ float g_part[2][GRID];
__device__ float g_alpha[KL];
__device__ float g_betav[KL];
__device__ unsigned int g_barcnt;
__device__ volatile unsigned int g_release;

// ---------------- CSR build ------------------------------------------------
__global__ void k_prep(const float* __restrict__ pred, const float* __restrict__ scl) {
    int i = blockIdx.x * blockDim.x + threadIdx.x;
    if (i < NNZ) g_vals[i] = pred[i] * scl[i];
    if (i < N)   g_cnt[i] = 0;
    if (blockIdx.x == 0 && threadIdx.x == 0) { g_barcnt = 0; g_release = 0; }
}
__global__ void k_count(const int* __restrict__ rows) {
    int i = blockIdx.x * blockDim.x + threadIdx.x;
    if (i < NNZ) atomicAdd(&g_cnt[rows[i]], 1);
}
__global__ void k_scan() {
    int tid = threadIdx.x;
    int lane = tid & 31, warp = tid >> 5;
    int v[8]; int loc = 0;
#pragma unroll
    for (int u = 0; u < 8; u++) { v[u] = g_cnt[tid*8 + u]; loc += v[u]; }
    int sc = loc;
#pragma unroll
    for (int off = 1; off < 32; off <<= 1) {
        int nb = __shfl_up_sync(0xffffffffu, sc, off);
        if (lane >= off) sc += nb;
    }
    __shared__ int wsum[8];
    if (lane == 31) wsum[warp] = sc;
    __syncthreads();
    if (tid == 0) {
        int a = 0;
#pragma unroll
        for (int w = 0; w < 8; w++) { int t = wsum[w]; wsum[w] = a; a += t; }
    }
    __syncthreads();
    int run = sc - loc + wsum[warp];
#pragma unroll
    for (int u = 0; u < 8; u++) {
        g_rowptr[tid*8 + u] = run;
        g_cnt[tid*8 + u]    = run;
        run += v[u];
    }
    if (tid == 255) g_rowptr[N] = run;
}
__global__ void k_fill(const int* __restrict__ rows, const int* __restrict__ cols) {
    int i = blockIdx.x * blockDim.x + threadIdx.x;
    if (i < NNZ) {
        int p = atomicAdd(&g_cnt[rows[i]], 1);
        g_colidx[p] = cols[i];
        g_csrval[p] = g_vals[i];
    }
}

// ------ SYRK split-K: 272 CTAs (2/SM), each does half of K ------------------
// half 0 -> raw partial into g_C, half 1 -> raw partial into g_CT.
__global__ void __launch_bounds__(256, 2) k_syrk(const float* __restrict__ Af) {
    const int cid = blockIdx.x;          // 0..271
    const int half = cid & 1;
    int rem = cid >> 1, by = 0;
    while (rem >= 16 - by) { rem -= 16 - by; by++; }
    const int bx = by + rem;

    __shared__ __align__(16) float As[2][BKS][132];
    __shared__ __align__(16) float Bs[2][BKS][132];
    const int tid = threadIdx.x;
    const int tx = tid & 15, ty = tid >> 4;
    const int row0 = by * 128, col0 = bx * 128;
    const int k0 = half * (N / 2);

    uint64_t acc2[8][4];
#pragma unroll
    for (int i = 0; i < 8; i++)
#pragma unroll
        for (int j = 0; j < 4; j++) acc2[i][j] = 0ull;

    const int lr = tid >> 1;
    const int lk = (tid & 1) * 8;
    const float* abase = Af + (size_t)(row0 + lr) * N + k0 + lk;
    const float* bbase = Af + (size_t)(col0 + lr) * N + k0 + lk;

    float4 pa0 = *(const float4*)(abase);
    float4 pa1 = *(const float4*)(abase + 4);
    float4 pb0 = *(const float4*)(bbase);
    float4 pb1 = *(const float4*)(bbase + 4);
    {
        As[0][lk+0][lr]=pa0.x; As[0][lk+1][lr]=pa0.y; As[0][lk+2][lr]=pa0.z; As[0][lk+3][lr]=pa0.w;
        As[0][lk+4][lr]=pa1.x; As[0][lk+5][lr]=pa1.y; As[0][lk+6][lr]=pa1.z; As[0][lk+7][lr]=pa1.w;
        Bs[0][lk+0][lr]=pb0.x; Bs[0][lk+1][lr]=pb0.y; Bs[0][lk+2][lr]=pb0.z; Bs[0][lk+3][lr]=pb0.w;
        Bs[0][lk+4][lr]=pb1.x; Bs[0][lk+5][lr]=pb1.y; Bs[0][lk+6][lr]=pb1.z; Bs[0][lk+7][lr]=pb1.w;
    }
    __syncthreads();

    const int NIT = (N / 2) / BKS;       // 64
    for (int it = 0; it < NIT; it++) {
        const int buf = it & 1;
        if (it + 1 < NIT) {
            int off = (it + 1) * BKS;
            pa0 = *(const float4*)(abase + off);
            pa1 = *(const float4*)(abase + off + 4);
            pb0 = *(const float4*)(bbase + off);
            pb1 = *(const float4*)(bbase + off + 4);
        }
#pragma unroll
        for (int k = 0; k < BKS; k++) {
            float4 a0 = *(const float4*)&As[buf][k][4*ty];
            float4 a1 = *(const float4*)&As[buf][k][64+4*ty];
            const uint64_t* bq0 = (const uint64_t*)&Bs[buf][k][4*tx];
            const uint64_t* bq1 = (const uint64_t*)&Bs[buf][k][64+4*tx];
            uint64_t bp0 = bq0[0], bp1 = bq0[1], bp2 = bq1[0], bp3 = bq1[1];
            float av[8] = {a0.x,a0.y,a0.z,a0.w,a1.x,a1.y,a1.z,a1.w};
#pragma unroll
            for (int i = 0; i < 8; i++) {
                uint64_t ap;
                asm("mov.b64 %0, {%1, %1};" : "=l"(ap) : "f"(av[i]));
                asm("fma.rn.f32x2 %0, %1, %2, %0;" : "+l"(acc2[i][0]) : "l"(ap), "l"(bp0));
                asm("fma.rn.f32x2 %0, %1, %2, %0;" : "+l"(acc2[i][1]) : "l"(ap), "l"(bp1));
                asm("fma.rn.f32x2 %0, %1, %2, %0;" : "+l"(acc2[i][2]) : "l"(ap), "l"(bp2));
                asm("fma.rn.f32x2 %0, %1, %2, %0;" : "+l"(acc2[i][3]) : "l"(ap), "l"(bp3));
            }
        }
        if (it + 1 < NIT) {
            const int nb = buf ^ 1;
            As[nb][lk+0][lr]=pa0.x; As[nb][lk+1][lr]=pa0.y; As[nb][lk+2][lr]=pa0.z; As[nb][lk+3][lr]=pa0.w;
            As[nb][lk+4][lr]=pa1.x; As[nb][lk+5][lr]=pa1.y; As[nb][lk+6][lr]=pa1.z; As[nb][lk+7][lr]=pa1.w;
            Bs[nb][lk+0][lr]=pb0.x; Bs[nb][lk+1][lr]=pb0.y; Bs[nb][lk+2][lr]=pb0.z; Bs[nb][lk+3][lr]=pb0.w;
            Bs[nb][lk+4][lr]=pb1.x; Bs[nb][lk+5][lr]=pb1.y; Bs[nb][lk+6][lr]=pb1.z; Bs[nb][lk+7][lr]=pb1.w;
        }
        __syncthreads();
    }

    float acc[8][8];
#pragma unroll
    for (int i = 0; i < 8; i++)
#pragma unroll
        for (int j = 0; j < 4; j++) {
            float lo, hi;
            asm("mov.b64 {%0, %1}, %2;" : "=f"(lo), "=f"(hi) : "l"(acc2[i][j]));
            acc[i][2*j]   = lo;
            acc[i][2*j+1] = hi;
        }

    float* dst = half ? g_CT : g_C;      // raw partial products
#pragma unroll
    for (int i = 0; i < 8; i++) {
        int gi = row0 + ((i<4) ? (4*ty+i) : (64+4*ty+i-4));
#pragma unroll
        for (int j = 0; j < 8; j++) {
            int gj = col0 + ((j<4) ? (4*tx+j) : (64+4*tx+j-4));
            float val = acc[i][j];
            dst[(size_t)gi*N+gj] = val;
            if (bx > by) dst[(size_t)gj*N+gi] = val;
        }
    }
}

// ------ combine: A = (P0 + P1)/N + I ----------------------------------------
__global__ void k_comb() {
    int i = blockIdx.x * blockDim.x + threadIdx.x;      // over N*N/4 float4
    float4 p0 = ((const float4*)g_C)[i];
    float4 p1 = ((const float4*)g_CT)[i];
    const float invn = 1.0f / (float)N;
    int base = i * 4;
    int r = base >> 11;          // row (N=2048)
    int c = base & (N - 1);      // col of .x
    float4 v;
    v.x = (p0.x + p1.x) * invn + ((r == c+0) ? 1.0f : 0.0f);
    v.y = (p0.y + p1.y) * invn + ((r == c+1) ? 1.0f : 0.0f);
    v.z = (p0.z + p1.z) * invn + ((r == c+2) ? 1.0f : 0.0f);
    v.w = (p0.w + p1.w) * invn + ((r == c+3) ? 1.0f : 0.0f);
    ((float4*)g_A)[i] = v;
}

// ---------------- SpMM 1: C = S * A ------------------------------------------
__global__ void k_spmm_AC() {
    int r = blockIdx.x, t = threadIdx.x;
    int s = g_rowptr[r], e = g_rowptr[r+1];
    float acc[8] = {0,0,0,0,0,0,0,0};
    for (int k = s; k < e; k++) {
        int c = g_colidx[k];
        float v = g_csrval[k];
        const float* xr = g_A + (size_t)c * N;
#pragma unroll
        for (int u = 0; u < 8; u++) acc[u] += v * xr[t + u*TPB];
    }
    float* yr = g_C + (size_t)r * N;
#pragma unroll
    for (int u = 0; u < 8; u++) yr[t + u*TPB] = acc[u];
}

// ---------------- transpose: CT = C^T ----------------------------------------
__global__ void k_tr_C_CT() {
    __shared__ float t[32][33];
    int bx = blockIdx.x*32, by = blockIdx.y*32;
    int x = bx + threadIdx.x;
#pragma unroll
    for (int j = 0; j < 32; j += 8)
        t[threadIdx.y+j][threadIdx.x] = g_C[(size_t)(by+threadIdx.y+j)*N + x];
    __syncthreads();
    int x2 = by + threadIdx.x;
#pragma unroll
    for (int j = 0; j < 32; j += 8)
        g_CT[(size_t)(bx+threadIdx.y+j)*N + x2] = t[threadIdx.x][threadIdx.y+j];
}

// ------- SpMM 2 fused: M = A + C + C^T + S*C^T ------------------------------
__global__ void k_spmm_M() {
    int r = blockIdx.x, t = threadIdx.x;
    int s = g_rowptr[r], e = g_rowptr[r+1];
    float acc[8] = {0,0,0,0,0,0,0,0};
    for (int k = s; k < e; k++) {
        int c = g_colidx[k];
        float v = g_csrval[k];
        const float* xr = g_CT + (size_t)c * N;
#pragma unroll
        for (int u = 0; u < 8; u++) acc[u] += v * xr[t + u*TPB];
    }
    const float* ar = g_A  + (size_t)r * N;
    const float* cr = g_C  + (size_t)r * N;
    const float* tr = g_CT + (size_t)r * N;
    float* mr = g_M + (size_t)r * N;
#pragma unroll
    for (int u = 0; u < 8; u++) {
        int i = t + u*TPB;
        mr[i] = ar[i] + cr[i] + tr[i] + acc[u];
    }
}

// ---------------- Lanczos + fused extremes (fold-normalize) -----------------
__device__ __forceinline__ void gbar(unsigned int& ep) {
    ep++;
    __threadfence();
    __syncthreads();
    if (threadIdx.x == 0) {
        unsigned int old = atomicAdd(&g_barcnt, 1u);
        if (old == GRID - 1u) {
            g_barcnt = 0;
            __threadfence();
            g_release = ep;
        } else {
            while (g_release < ep) { }
        }
    }
    __syncthreads();
    __threadfence();
}

__device__ __forceinline__ float sum_parts(const float* part, float* sred, float* sbc) {
    int tid = threadIdx.x, warp = tid >> 5, wl = tid & 31;
    float a = (tid < GRID) ? __ldcg(&part[tid]) : 0.f;
#pragma unroll
    for (int off = 16; off; off >>= 1) a += __shfl_down_sync(0xffffffffu, a, off);
    if (wl == 0) sred[warp] = a;
    __syncthreads();
    if (tid == 0) {
        float s = 0.f;
#pragma unroll
        for (int w = 0; w < 4; w++) s += sred[w];
        sbc[0] = s;
    }
    __syncthreads();
    return sbc[0];
}

__device__ __forceinline__ float block_sum(float p, float* sred, float* sbc) {
    int tid = threadIdx.x, warp = tid >> 5, wl = tid & 31;
#pragma unroll
    for (int off = 16; off; off >>= 1) p += __shfl_down_sync(0xffffffffu, p, off);
    if (wl == 0) sred[warp] = p;
    __syncthreads();
    if (tid == 0) {
        float s = 0.f;
#pragma unroll
        for (int w = 0; w < 8; w++) s += sred[w];
        sbc[0] = s;
    }
    __syncthreads();
    return sbc[0];
}

__global__ void __launch_bounds__(TPB) k_lanczos(float* out) {
    __shared__ __align__(16) float svbuf[2][N];   // RAW vectors (scale folded)
    __shared__ float shw[16];
    __shared__ float sred[8];
    __shared__ float sbc[1];

    const int tid = threadIdx.x, bid = blockIdx.x;
    const int q = tid >> 4, lane = tid & 15;
    const int row = bid*16 + q;
    const int myrow = bid*16 + tid;
    unsigned int ep = 0;

    if (tid < 16) {
        unsigned int h = (unsigned int)myrow * 2654435761u + 0x9E3779B9u;
        h ^= h>>16; h *= 0x85ebca6bu; h ^= h>>13; h *= 0xc2b2ae35u; h ^= h>>16;
        g_u[1][myrow] = (float)(h & 0xffffu) * (1.0f/65536.0f) + 0.0625f;
    }
    gbar(ep);

    float* svc = svbuf[0];
    float* svp = svbuf[1];
    float inv_c, inv_p = 0.f, beta_p = 0.f;
    {
        float p = 0.f;
        for (int i = tid; i < N; i += TPB) {
            float x = __ldcg(&g_u[1][i]);
            svc[i] = x;                  // raw start vector
            svp[i] = 0.f;
            p += x * x;
        }
        float n0 = block_sum(p, sred, sbc);
        inv_c = rsqrtf(n0);              // scale of svc
        __syncthreads();
    }

    for (int j = 0; j < KL; j++) {
        const int b = j & 1;
        // matvec on RAW svc
        const float4* M4  = ((const float4*)g_M) + (size_t)row * (N/4);
        const float4* sv4 = (const float4*)svc;
        float s = 0.f;
#pragma unroll
        for (int t = 0; t < 16; t++) {
            int qi = lane*2 + t*32;
            float4 m0 = M4[qi], m1 = M4[qi+1];
            float4 x0 = sv4[qi], x1 = sv4[qi+1];
            s += m0.x*x0.x + m0.y*x0.y + m0.z*x0.z + m0.w*x0.w
               + m1.x*x1.x + m1.y*x1.y + m1.z*x1.z + m1.w*x1.w;
        }
#pragma unroll
        for (int off = 8; off; off >>= 1) s += __shfl_down_sync(0xffffffffu, s, off, 16);
        if (lane == 0) shw[q] = s;
        __syncthreads();

        // publish TRUE u = s_raw * inv_c; pa = u . v_true
        float pa = 0.f;
        if (tid < 16) {
            float uval = shw[tid] * inv_c;
            g_u[b][myrow] = uval;
            pa = uval * (svc[myrow] * inv_c);
        }
#pragma unroll
        for (int off = 8; off; off >>= 1) pa += __shfl_down_sync(0xffffffffu, pa, off, 16);
        if (tid == 0) g_part[b][bid] = pa;
        gbar(ep);

        float alpha = sum_parts(g_part[b], sred, sbc);
        const float ac = alpha  * inv_c;     // coeff on raw svc
        const float bc = beta_p * inv_p;     // coeff on raw svp
        float pw = 0.f;
        for (int i = tid; i < N; i += TPB) {
            float w = __ldcg(&g_u[b][i]) - ac*svc[i] - bc*svp[i];
            svp[i] = w;                  // w is TRUE w (raw v_{j+1}, scale 1/beta)
            pw += w * w;
        }
        float nw = block_sum(pw, sred, sbc);
        float beta = sqrtf(fmaxf(nw, 1e-30f));
        if (bid == 0 && tid == 0) { g_alpha[j] = alpha; g_betav[j] = beta; }
        __syncthreads();
        float* t = svc; svc = svp; svp = t;
        inv_p = inv_c;
        inv_c = 1.0f / beta;
        beta_p = beta;
    }

    // ---- fused extremes: block 0 only
    if (bid != 0) return;
    __shared__ double sa[KL], sb[KL];
    __shared__ double sbounds[2];
    __shared__ double res[2];
    for (int i = tid; i < KL; i += TPB) {
        sa[i] = (double)g_alpha[i];
        sb[i] = (double)g_betav[i];
    }
    __syncthreads();
    if (tid == 0) {
        double lo = 1e300, hi = -1e300;
        for (int i = 0; i < KL; i++) {
            double bl = (i > 0)    ? fabs(sb[i-1]) : 0.0;
            double br = (i < KL-1) ? fabs(sb[i])   : 0.0;
            double a = sa[i];
            if (a - bl - br < lo) lo = a - bl - br;
            if (a + bl + br > hi) hi = a + bl + br;
        }
        sbounds[0] = lo; sbounds[1] = hi;
    }
    __syncthreads();
    if (tid < 64) {
        int warp = tid >> 5, wl = tid & 31;
        int target = (warp == 0) ? KL : 1;
        double lo = sbounds[0], hi = sbounds[1];
        for (int step = 0; step < 4; step++) {
            double w = (hi - lo) * (1.0 / 33.0);
            double x = lo + w * (double)(wl + 1);
            double d = sa[0] - x;
            int cnt = (d < 0.0);
            for (int i = 1; i < KL; i++) {
                double den = d;
                if (fabs(den) < 1e-280) den = (den < 0.0) ? -1e-280 : 1e-280;
                d = (sa[i] - x) - sb[i-1]*sb[i-1] / den;
                cnt += (d < 0.0);
            }
            unsigned mask = __ballot_sync(0xffffffffu, cnt >= target);
            int first = (mask == 0u) ? 32 : (__ffs(mask) - 1);
            if (first < 32) hi = lo + w * (double)(first + 1);
            lo = lo + w * (double)first;
        }
        if (wl == 0) res[warp] = 0.5 * (lo + hi);
    }
    __syncthreads();
    if (tid == 0) {
        double lmax = fmax(res[0], 1e-12);
        double lmin = fmax(res[1], 1e-12);
        out[0] = (float)(log(lmax) - log(lmin));
    }
}

// ---------------- launch ------------------------------------------------------
extern "C" void kernel_launch(void* const* d_in, const int* in_sizes, int n_in,
                              void* d_out, int out_size) {
    const float* pred = (const float*)d_in[0];
    const float* scl  = (const float*)d_in[1];
    const float* Af   = (const float*)d_in[2];
    const int* frows  = (const int*)d_in[3];
    const int* fcols  = (const int*)d_in[4];
    float* out = (float*)d_out;

    k_prep <<<NNZ/TPB, TPB>>>(pred, scl);
    k_count<<<NNZ/TPB, TPB>>>(frows);
    k_scan <<<1, 256>>>();
    k_syrk <<<2*SYRK_TILES, 256>>>(Af);   // 4th launch -> captured by ncu
    k_fill <<<NNZ/TPB, TPB>>>(frows, fcols);
    k_comb <<<N*N/4/TPB, TPB>>>();

    k_spmm_AC <<<N, TPB>>>();
    k_tr_C_CT <<<dim3(64,64), dim3(32,8)>>>();
    k_spmm_M  <<<N, TPB>>>();

    k_lanczos <<<GRID, TPB>>>(out);
}